// round 3
// baseline (speedup 1.0000x reference)
#include <cuda_runtime.h>
#include <cuda_bf16.h>
#include <stdint.h>
#include <cstdint>
#include <math.h>

// Problem constants (fixed shapes per reference)
#define NN   50000
#define EE   800000
#define IN_D 256
#define HC   256      // H*C
#define HH   4
#define CC   64
#define LAT  32

// ---------------- device scratch (globals: no allocation allowed) ----------
__device__ float g_xl[NN * HC];      // 51.2 MB
__device__ float g_xr[NN * HC];      // 51.2 MB
__device__ float g_h [NN * CC];      // 12.8 MB
__device__ float g_loop[NN * 3];
__device__ int   g_deg [NN];
__device__ int   g_off [NN + 1];
__device__ int   g_fill[NN];
__device__ int   g_csr [EE];
__device__ int   g_bsum[64];
__device__ int   g_boff[64];

// ---------------- graph preprocessing ---------------------------------------
__global__ void init_kernel() {
    int i = blockIdx.x * blockDim.x + threadIdx.x;
    if (i < NN) { g_deg[i] = 0; g_fill[i] = 0; }
}

__global__ void edge_deg_kernel(const int* __restrict__ dst) {
    int e = blockIdx.x * blockDim.x + threadIdx.x;
    if (e >= EE) return;
    atomicAdd(&g_deg[dst[e]], 1);
}

// coalesced 3-stage scan of g_deg -> g_off (exclusive)
__global__ void deg_blocksum_kernel() {     // grid 49, block 1024
    int i = blockIdx.x * 1024 + threadIdx.x;
    int v = (i < NN) ? g_deg[i] : 0;
    __shared__ int ws[32];
    int lane = threadIdx.x & 31, wid = threadIdx.x >> 5;
    #pragma unroll
    for (int o = 16; o > 0; o >>= 1) v += __shfl_down_sync(0xffffffff, v, o);
    if (lane == 0) ws[wid] = v;
    __syncthreads();
    if (wid == 0) {
        int s = ws[lane];
        #pragma unroll
        for (int o = 16; o > 0; o >>= 1) s += __shfl_down_sync(0xffffffff, s, o);
        if (lane == 0) g_bsum[blockIdx.x] = s;
    }
}

__global__ void bsum_scan_kernel(int nblk) {  // <<<1,1>>>
    int run = 0;
    for (int i = 0; i < nblk; i++) { g_boff[i] = run; run += g_bsum[i]; }
    g_off[NN] = run;
}

__global__ void off_write_kernel() {        // grid 49, block 1024
    __shared__ int s[1024];
    int t = threadIdx.x;
    int i = blockIdx.x * 1024 + t;
    int v = (i < NN) ? g_deg[i] : 0;
    s[t] = v;
    __syncthreads();
    #pragma unroll
    for (int o = 1; o < 1024; o <<= 1) {
        int u = (t >= o) ? s[t - o] : 0;
        __syncthreads();
        s[t] += u;
        __syncthreads();
    }
    if (i < NN) g_off[i] = g_boff[blockIdx.x] + s[t] - v;
}

__global__ void csr_fill_kernel(const int* __restrict__ dst) {
    int e = blockIdx.x * blockDim.x + threadIdx.x;
    if (e >= EE) return;
    int d = dst[e];
    int pos = g_off[d] + atomicAdd(&g_fill[d], 1);
    g_csr[pos] = e;
}

// self-loop attr = mean of incoming edge_attr (warp per node, no atomics)
__global__ __launch_bounds__(256)
void loop_attr_kernel(const float* __restrict__ ea) {
    int warp = (blockIdx.x * blockDim.x + threadIdx.x) >> 5;
    if (warp >= NN) return;
    int lane = threadIdx.x & 31;
    int e0 = g_off[warp], e1 = g_off[warp + 1];
    float s0 = 0.f, s1 = 0.f, s2 = 0.f;
    for (int t = e0 + lane; t < e1; t += 32) {
        int e = g_csr[t];
        s0 += ea[e * 3 + 0];
        s1 += ea[e * 3 + 1];
        s2 += ea[e * 3 + 2];
    }
    #pragma unroll
    for (int o = 16; o > 0; o >>= 1) {
        s0 += __shfl_xor_sync(0xffffffff, s0, o);
        s1 += __shfl_xor_sync(0xffffffff, s1, o);
        s2 += __shfl_xor_sync(0xffffffff, s2, o);
    }
    if (lane == 0) {
        float inv = 1.f / fmaxf((float)(e1 - e0), 1.f);
        g_loop[warp * 3 + 0] = s0 * inv;
        g_loop[warp * 3 + 1] = s1 * inv;
        g_loop[warp * 3 + 2] = s2 * inv;
    }
}

// ---------------- tf32 tensor-core GEMM (3xTF32, fp32-accurate) -------------
// C[M,256] = A[M,K] @ B[K,256] + bias.  BM=128, BN=64, BK=32, 256 threads.
__device__ __forceinline__ uint32_t f2tf32(float x) {
    uint32_t r;
    asm("cvt.rna.tf32.f32 %0, %1;" : "=r"(r) : "f"(x));
    return r;
}

__device__ __forceinline__ void mma_tf32(float* c, const uint32_t* a, const uint32_t* b) {
    asm volatile(
        "mma.sync.aligned.m16n8k8.row.col.f32.tf32.tf32.f32 "
        "{%0,%1,%2,%3}, {%4,%5,%6,%7}, {%8,%9}, {%0,%1,%2,%3};"
        : "+f"(c[0]), "+f"(c[1]), "+f"(c[2]), "+f"(c[3])
        : "r"(a[0]), "r"(a[1]), "r"(a[2]), "r"(a[3]), "r"(b[0]), "r"(b[1]));
}

__global__ __launch_bounds__(256)
void gemm_tf32_kernel(const float* __restrict__ A, const float* __restrict__ B,
                      const float* __restrict__ bias, float* __restrict__ C,
                      int M, int K) {
    // fragment-native SMEM layouts, hi plane then lo plane
    __shared__ uint32_t sA[8192];   // [hl:4096][k8:1024][m16:128][lane*4+r]
    __shared__ uint32_t sB[4096];   // [hl:2048][k8:512 ][n8:64 ][lane*2+r]

    const int tid  = threadIdx.x;
    const int lane = tid & 31;
    const int w    = tid >> 5;
    const int wm   = w >> 1;        // 0..3 (32 rows each)
    const int wn   = w & 1;         // 0..1 (32 cols each)
    const int bm   = blockIdx.x * 128;
    const int bn   = blockIdx.y * 64;
    const int NC   = HC;            // 256

    // --- precompute per-thread scatter offsets (chunk-invariant) ---
    int arow[4], acol0[4], abase[4];
    #pragma unroll
    for (int i = 0; i < 4; i++) {
        int f = tid + i * 256;          // 1024 float4 of A tile
        int row = f >> 3, colv = f & 7;
        arow[i] = row; acol0[i] = colv * 4;
        int k8 = colv >> 1, rhalf = colv & 1;
        int m16 = row >> 4, g = row & 7, rbit = (row >> 3) & 1;
        abase[i] = k8 * 1024 + m16 * 128 + g * 16 + (rbit | (rhalf << 1));
    }
    int brow[2], bcol0[2], bbase[2];
    #pragma unroll
    for (int i = 0; i < 2; i++) {
        int f = tid + i * 256;          // 512 float4 of B tile
        int krow = f >> 4, colv = f & 15;
        brow[i] = krow; bcol0[i] = colv * 4;
        int k8 = krow >> 3, kk = krow & 7;
        int t = kk & 3, r = kk >> 2;
        int n8 = colv >> 1, g0 = (colv & 1) * 4;
        bbase[i] = k8 * 512 + n8 * 64 + (g0 * 4 + t) * 2 + r;
    }

    float acc[2][4][4];
    #pragma unroll
    for (int m = 0; m < 2; m++)
        #pragma unroll
        for (int n = 0; n < 4; n++)
            #pragma unroll
            for (int r = 0; r < 4; r++) acc[m][n][r] = 0.f;

    const int nchunk = K >> 5;
    float4 av[4], bv[2];

    // prefetch chunk 0
    #pragma unroll
    for (int i = 0; i < 4; i++) {
        int gr = bm + arow[i];
        av[i] = (gr < M) ? *(const float4*)(A + (size_t)gr * K + acol0[i])
                         : make_float4(0.f, 0.f, 0.f, 0.f);
    }
    #pragma unroll
    for (int i = 0; i < 2; i++)
        bv[i] = *(const float4*)(B + (size_t)brow[i] * NC + bn + bcol0[i]);

    for (int ch = 0; ch < nchunk; ch++) {
        // store prefetched regs -> smem with hi/lo split
        #pragma unroll
        for (int i = 0; i < 4; i++) {
            float e[4] = {av[i].x, av[i].y, av[i].z, av[i].w};
            #pragma unroll
            for (int t = 0; t < 4; t++) {
                uint32_t hi = f2tf32(e[t]);
                uint32_t lo = f2tf32(e[t] - __uint_as_float(hi));
                sA[abase[i] + t * 4]        = hi;
                sA[4096 + abase[i] + t * 4] = lo;
            }
        }
        #pragma unroll
        for (int i = 0; i < 2; i++) {
            float e[4] = {bv[i].x, bv[i].y, bv[i].z, bv[i].w};
            #pragma unroll
            for (int j = 0; j < 4; j++) {
                uint32_t hi = f2tf32(e[j]);
                uint32_t lo = f2tf32(e[j] - __uint_as_float(hi));
                sB[bbase[i] + j * 8]        = hi;
                sB[2048 + bbase[i] + j * 8] = lo;
            }
        }
        __syncthreads();

        // prefetch next chunk
        if (ch + 1 < nchunk) {
            int k0 = (ch + 1) * 32;
            #pragma unroll
            for (int i = 0; i < 4; i++) {
                int gr = bm + arow[i];
                av[i] = (gr < M) ? *(const float4*)(A + (size_t)gr * K + k0 + acol0[i])
                                 : make_float4(0.f, 0.f, 0.f, 0.f);
            }
            #pragma unroll
            for (int i = 0; i < 2; i++)
                bv[i] = *(const float4*)(B + (size_t)(k0 + brow[i]) * NC + bn + bcol0[i]);
        }

        // compute: 4 k8 steps
        #pragma unroll
        for (int k8 = 0; k8 < 4; k8++) {
            uint32_t ah[2][4], al[2][4], bh[4][2], bl[4][2];
            #pragma unroll
            for (int m = 0; m < 2; m++) {
                const uint4* ph = (const uint4*)&sA[k8 * 1024 + (wm * 2 + m) * 128 + lane * 4];
                const uint4* pl = (const uint4*)&sA[4096 + k8 * 1024 + (wm * 2 + m) * 128 + lane * 4];
                uint4 vh = *ph, vl = *pl;
                ah[m][0] = vh.x; ah[m][1] = vh.y; ah[m][2] = vh.z; ah[m][3] = vh.w;
                al[m][0] = vl.x; al[m][1] = vl.y; al[m][2] = vl.z; al[m][3] = vl.w;
            }
            #pragma unroll
            for (int n = 0; n < 4; n++) {
                const uint2* ph = (const uint2*)&sB[k8 * 512 + (wn * 4 + n) * 64 + lane * 2];
                const uint2* pl = (const uint2*)&sB[2048 + k8 * 512 + (wn * 4 + n) * 64 + lane * 2];
                uint2 vh = *ph, vl = *pl;
                bh[n][0] = vh.x; bh[n][1] = vh.y;
                bl[n][0] = vl.x; bl[n][1] = vl.y;
            }
            #pragma unroll
            for (int m = 0; m < 2; m++)
                #pragma unroll
                for (int n = 0; n < 4; n++) {
                    mma_tf32(acc[m][n], al[m], bh[n]);
                    mma_tf32(acc[m][n], ah[m], bl[n]);
                    mma_tf32(acc[m][n], ah[m], bh[n]);
                }
        }
        __syncthreads();
    }

    // epilogue: bias add + store
    const int g = lane >> 2, t = lane & 3;
    #pragma unroll
    for (int m = 0; m < 2; m++) {
        int r0 = bm + wm * 32 + m * 16 + g;
        #pragma unroll
        for (int n = 0; n < 4; n++) {
            int col = bn + wn * 32 + n * 8 + t * 2;
            float b0 = bias[col], b1 = bias[col + 1];
            if (r0 < M) {
                float2 v = make_float2(acc[m][n][0] + b0, acc[m][n][1] + b1);
                *(float2*)(C + (size_t)r0 * NC + col) = v;
            }
            if (r0 + 8 < M) {
                float2 v = make_float2(acc[m][n][2] + b0, acc[m][n][3] + b1);
                *(float2*)(C + (size_t)(r0 + 8) * NC + col) = v;
            }
        }
    }
}

// ---------------- GATv2 aggregation: one warp per dst node ------------------
__global__ __launch_bounds__(256)
void gat_agg_kernel(const float* __restrict__ xl, const float* __restrict__ xr,
                    const float* __restrict__ edge_attr,
                    const int* __restrict__ srcarr,
                    const float* __restrict__ We, const float* __restrict__ att,
                    const float* __restrict__ bias, float* __restrict__ out) {
    int warp = (blockIdx.x * blockDim.x + threadIdx.x) >> 5;
    if (warp >= NN) return;
    int lane  = threadIdx.x & 31;
    int node  = warp;
    int jbase = lane * 8;

    float we0[8], we1[8], we2[8], attv[8], xrv[8];
    #pragma unroll
    for (int i = 0; i < 8; i++) {
        int j = jbase + i;
        we0[i]  = We[j];
        we1[i]  = We[256 + j];
        we2[i]  = We[512 + j];
        attv[i] = att[j];
        xrv[i]  = xr[(size_t)node * HC + j];
    }

    float mx = -1e30f, denom = 0.f;
    float acc[8] = {};
    int e0 = g_off[node], e1 = g_off[node + 1];

    for (int t = e0; t <= e1; t++) {      // last iteration = self loop
        int s; float ea0, ea1, ea2;
        if (t < e1) {
            int e = g_csr[t];
            s = srcarr[e];
            ea0 = edge_attr[e * 3 + 0];
            ea1 = edge_attr[e * 3 + 1];
            ea2 = edge_attr[e * 3 + 2];
        } else {
            s = node;
            ea0 = g_loop[node * 3 + 0];
            ea1 = g_loop[node * 3 + 1];
            ea2 = g_loop[node * 3 + 2];
        }
        float xlv[8];
        const float4* p = (const float4*)(xl + (size_t)s * HC + jbase);
        float4 v0 = p[0], v1 = p[1];
        xlv[0] = v0.x; xlv[1] = v0.y; xlv[2] = v0.z; xlv[3] = v0.w;
        xlv[4] = v1.x; xlv[5] = v1.y; xlv[6] = v1.z; xlv[7] = v1.w;

        float part = 0.f;
        #pragma unroll
        for (int i = 0; i < 8; i++) {
            float m = xlv[i] + xrv[i] + ea0 * we0[i] + ea1 * we1[i] + ea2 * we2[i];
            m = (m > 0.f) ? m : 0.2f * m;
            part += m * attv[i];
        }
        part += __shfl_xor_sync(0xffffffff, part, 1);
        part += __shfl_xor_sync(0xffffffff, part, 2);
        part += __shfl_xor_sync(0xffffffff, part, 4);
        float alpha = part;

        float nm = fmaxf(mx, alpha);
        float sc = __expf(mx - nm);
        float pw = __expf(alpha - nm);
        denom = denom * sc + pw;
        #pragma unroll
        for (int i = 0; i < 8; i++) acc[i] = acc[i] * sc + pw * xlv[i];
        mx = nm;
    }

    float inv = 1.f / denom;
    #pragma unroll
    for (int i = 0; i < 8; i++) {
        float r = acc[i] * inv;
        r += __shfl_xor_sync(0xffffffff, r, 8);
        r += __shfl_xor_sync(0xffffffff, r, 16);
        acc[i] = r * 0.25f;
    }
    if (lane < 8) {
        #pragma unroll
        for (int i = 0; i < 8; i++) {
            int c = jbase + i;
            out[(size_t)node * CC + c] = fmaxf(acc[i] + bias[c], 0.f);
        }
    }
}

// ---------------- final projection: out = h @ Wmu + bmu ---------------------
__global__ __launch_bounds__(256)
void mu_kernel(const float* __restrict__ h, const float* __restrict__ Wmu,
               const float* __restrict__ bmu, float* __restrict__ out) {
    __shared__ float sW[CC * LAT];
    __shared__ float sb[LAT];
    int tid = threadIdx.x;
    for (int i = tid; i < CC * LAT; i += 256) sW[i] = Wmu[i];
    if (tid < LAT) sb[tid] = bmu[tid];
    __syncthreads();
    int warp = tid >> 5, lane = tid & 31;
    int node = blockIdx.x * 8 + warp;
    if (node >= NN) return;
    const float* hr = h + (size_t)node * CC;
    float sum = sb[lane];
    #pragma unroll
    for (int c = 0; c < CC; c++)
        sum += hr[c] * sW[c * LAT + lane];
    out[(size_t)node * LAT + lane] = sum;
}

// ---------------- host launcher ---------------------------------------------
extern "C" void kernel_launch(void* const* d_in, const int* in_sizes, int n_in,
                              void* d_out, int out_size) {
    const float* x   = (const float*)d_in[0];
    const int*   ei  = (const int*)  d_in[1];
    const float* ea  = (const float*)d_in[2];
    const float* Wl0 = (const float*)d_in[3];
    const float* bl0 = (const float*)d_in[4];
    const float* Wr0 = (const float*)d_in[5];
    const float* br0 = (const float*)d_in[6];
    const float* We0 = (const float*)d_in[7];
    const float* at0 = (const float*)d_in[8];
    const float* bi0 = (const float*)d_in[9];
    const float* Wl1 = (const float*)d_in[10];
    const float* bl1 = (const float*)d_in[11];
    const float* Wr1 = (const float*)d_in[12];
    const float* br1 = (const float*)d_in[13];
    const float* We1 = (const float*)d_in[14];
    const float* at1 = (const float*)d_in[15];
    const float* bi1 = (const float*)d_in[16];
    const float* Wmu = (const float*)d_in[17];
    const float* bmu = (const float*)d_in[18];
    float* out = (float*)d_out;

    const int* src = ei;        // row 0
    const int* dst = ei + EE;   // row 1

    float* xl; cudaGetSymbolAddress((void**)&xl, g_xl);
    float* xr; cudaGetSymbolAddress((void**)&xr, g_xr);
    float* h ; cudaGetSymbolAddress((void**)&h , g_h );

    const int SCAN_BLOCKS = (NN + 1023) / 1024;   // 49

    // ---- graph preprocessing ----
    init_kernel<<<(NN + 255) / 256, 256>>>();
    edge_deg_kernel<<<(EE + 255) / 256, 256>>>(dst);
    deg_blocksum_kernel<<<SCAN_BLOCKS, 1024>>>();
    bsum_scan_kernel<<<1, 1>>>(SCAN_BLOCKS);
    off_write_kernel<<<SCAN_BLOCKS, 1024>>>();
    csr_fill_kernel<<<(EE + 255) / 256, 256>>>(dst);
    loop_attr_kernel<<<(NN + 7) / 8, 256>>>(ea);

    dim3 gemm_grid((NN + 127) / 128, HC / 64);
    dim3 agg_grid((NN + 7) / 8);

    // ---- layer 0 ----
    gemm_tf32_kernel<<<gemm_grid, 256>>>(x, Wl0, bl0, xl, NN, IN_D);
    gemm_tf32_kernel<<<gemm_grid, 256>>>(x, Wr0, br0, xr, NN, IN_D);
    gat_agg_kernel<<<agg_grid, 256>>>(xl, xr, ea, src, We0, at0, bi0, h);

    // ---- layer 1 ----
    gemm_tf32_kernel<<<gemm_grid, 256>>>(h, Wl1, bl1, xl, NN, CC);
    gemm_tf32_kernel<<<gemm_grid, 256>>>(h, Wr1, br1, xr, NN, CC);
    gat_agg_kernel<<<agg_grid, 256>>>(xl, xr, ea, src, We1, at1, bi1, h);

    // ---- projection ----
    mu_kernel<<<(NN + 7) / 8, 256>>>(h, Wmu, bmu, out);
}

// round 5
// speedup vs baseline: 1.3785x; 1.3785x over previous
#include <cuda_runtime.h>
#include <cuda_bf16.h>
#include <stdint.h>
#include <cstdint>
#include <math.h>

// Problem constants
#define NN   50000
#define EE   800000
#define IN_D 256
#define HC   256
#define HH   4
#define CC   64
#define LAT  32
#define MT   391          // ceil(50000/128)

// ---------------- device scratch ------------------------------------------
__device__ float g_xl[NN * HC];
__device__ float g_xr[NN * HC];
__device__ float g_h [NN * CC];
__device__ uint32_t g_aph[MT * 128 * 256];   // A hi plane, fragment-permuted (51.2MB)
__device__ uint32_t g_apl[MT * 128 * 256];   // A lo plane
__device__ uint32_t g_wph[4 * 65536];        // W hi planes, fragment-permuted
__device__ uint32_t g_wpl[4 * 65536];
__device__ int   g_deg [NN];
__device__ int   g_off [NN + 1];
__device__ int   g_fill[NN];
__device__ int   g_csr [EE];
__device__ int   g_bsum[64];
__device__ int   g_boff[64];

// ---------------- helpers ---------------------------------------------------
__device__ __forceinline__ uint32_t smem_u32(const void* p) {
    uint32_t a;
    asm("{ .reg .u64 t; cvta.to.shared.u64 t, %1; cvt.u32.u64 %0, t; }" : "=r"(a) : "l"(p));
    return a;
}
__device__ __forceinline__ uint32_t f2tf32(float x) {
    uint32_t r;
    asm("cvt.rna.tf32.f32 %0, %1;" : "=r"(r) : "f"(x));
    return r;
}
__device__ __forceinline__ void split_tf32(float v, uint32_t& hi, uint32_t& lo) {
    hi = f2tf32(v);
    lo = f2tf32(v - __uint_as_float(hi));
}
__device__ __forceinline__ void mma_tf32(float* c, const uint32_t* a, const uint32_t* b) {
    asm volatile(
        "mma.sync.aligned.m16n8k8.row.col.f32.tf32.tf32.f32 "
        "{%0,%1,%2,%3}, {%4,%5,%6,%7}, {%8,%9}, {%0,%1,%2,%3};"
        : "+f"(c[0]), "+f"(c[1]), "+f"(c[2]), "+f"(c[3])
        : "r"(a[0]), "r"(a[1]), "r"(a[2]), "r"(a[3]), "r"(b[0]), "r"(b[1]));
}
#define CP_ASYNC16(dst, src) \
    asm volatile("cp.async.ca.shared.global [%0], [%1], 16;" :: "r"((uint32_t)(dst)), "l"(src))
#define CP_COMMIT  asm volatile("cp.async.commit_group;" ::: "memory")
#define CP_WAIT(n) asm volatile("cp.async.wait_group %0;" :: "n"(n) : "memory")

// ---------------- graph preprocessing ---------------------------------------
__global__ void init_kernel() {
    int i = blockIdx.x * blockDim.x + threadIdx.x;
    if (i < NN) { g_deg[i] = 0; g_fill[i] = 0; }
}

__global__ void edge_deg_kernel(const int* __restrict__ dst) {
    int e = blockIdx.x * blockDim.x + threadIdx.x;
    if (e >= EE) return;
    atomicAdd(&g_deg[dst[e]], 1);
}

__global__ void deg_blocksum_kernel() {
    int i = blockIdx.x * 1024 + threadIdx.x;
    int v = (i < NN) ? g_deg[i] : 0;
    __shared__ int ws[32];
    int lane = threadIdx.x & 31, wid = threadIdx.x >> 5;
    #pragma unroll
    for (int o = 16; o > 0; o >>= 1) v += __shfl_down_sync(0xffffffff, v, o);
    if (lane == 0) ws[wid] = v;
    __syncthreads();
    if (wid == 0) {
        int s = ws[lane];
        #pragma unroll
        for (int o = 16; o > 0; o >>= 1) s += __shfl_down_sync(0xffffffff, s, o);
        if (lane == 0) g_bsum[blockIdx.x] = s;
    }
}

__global__ void bsum_scan_kernel(int nblk) {
    int run = 0;
    for (int i = 0; i < nblk; i++) { g_boff[i] = run; run += g_bsum[i]; }
    g_off[NN] = run;
}

__global__ void off_write_kernel() {
    __shared__ int s[1024];
    int t = threadIdx.x;
    int i = blockIdx.x * 1024 + t;
    int v = (i < NN) ? g_deg[i] : 0;
    s[t] = v;
    __syncthreads();
    #pragma unroll
    for (int o = 1; o < 1024; o <<= 1) {
        int u = (t >= o) ? s[t - o] : 0;
        __syncthreads();
        s[t] += u;
        __syncthreads();
    }
    if (i < NN) g_off[i] = g_boff[blockIdx.x] + s[t] - v;
}

__global__ void csr_fill_kernel(const int* __restrict__ dst) {
    int e = blockIdx.x * blockDim.x + threadIdx.x;
    if (e >= EE) return;
    int d = dst[e];
    int pos = g_off[d] + atomicAdd(&g_fill[d], 1);
    g_csr[pos] = e;
}

// ---------------- A conversion: fp32 row-major -> tf32 hi/lo fragment order --
// layout: [mt][kq][m16:8][lane:32][reg:4], mma m16n8k8 A-fragment order.
__global__ void convertA_kernel(const float* __restrict__ src, int K, int KQ) {
    int id = blockIdx.x * 256 + threadIdx.x;
    int total = MT * KQ * 256;
    if (id >= total) return;
    int lane = id & 31;
    int t = id >> 5;
    int m16 = t & 7; t >>= 3;
    int kq = t % KQ;
    int mt = t / KQ;
    int g = lane >> 2, tig = lane & 3;
    int row = mt * 128 + m16 * 16 + g;
    int col = kq * 8 + tig;
    float v0 = (row     < NN) ? src[(size_t)row * K + col]           : 0.f;
    float v1 = (row + 8 < NN) ? src[(size_t)(row + 8) * K + col]     : 0.f;
    float v2 = (row     < NN) ? src[(size_t)row * K + col + 4]       : 0.f;
    float v3 = (row + 8 < NN) ? src[(size_t)(row + 8) * K + col + 4] : 0.f;
    uint4 h, l;
    split_tf32(v0, h.x, l.x);
    split_tf32(v1, h.y, l.y);
    split_tf32(v2, h.z, l.z);
    split_tf32(v3, h.w, l.w);
    *(uint4*)(g_aph + (size_t)id * 4) = h;
    *(uint4*)(g_apl + (size_t)id * 4) = l;
}

// ---------------- W conversion: [K][256] -> tf32 hi/lo B-fragment order ------
// layout per widx: [kq][n8:32][lane:32][reg:2], mma m16n8k8 B-fragment order.
__global__ void convertW_kernel(const float* __restrict__ Wl0, const float* __restrict__ Wr0,
                                const float* __restrict__ Wl1, const float* __restrict__ Wr1) {
    int id = blockIdx.x * 256 + threadIdx.x;   // total 4*32*32*32 = 131072
    int widx = id >> 15;
    int rem = id & 32767;
    int kq = rem >> 10;
    int n8 = (rem >> 5) & 31;
    int lane = rem & 31;
    int KQw = (widx < 2) ? 32 : 8;
    if (kq >= KQw) return;
    const float* W = (widx == 0) ? Wl0 : (widx == 1) ? Wr0 : (widx == 2) ? Wl1 : Wr1;
    int g = lane >> 2, tig = lane & 3;
    int n = n8 * 8 + g;
    float v0 = W[(size_t)(kq * 8 + tig) * 256 + n];
    float v1 = W[(size_t)(kq * 8 + 4 + tig) * 256 + n];
    uint32_t h0, l0, h1, l1;
    split_tf32(v0, h0, l0);
    split_tf32(v1, h1, l1);
    int off = widx * 65536 + (kq * 2048 + n8 * 64 + lane * 2);
    g_wph[off] = h0; g_wph[off + 1] = h1;
    g_wpl[off] = l0; g_wpl[off + 1] = l1;
}

// ---------------- tf32 tensor GEMM: C[M,256] = A @ W + bias ------------------
// BM=128, BN=128 (grid.y=2), BK=32, 256 threads, 2-stage cp.async pipeline.
// SMEM stage (bytes): Ah @0, Al @16384, Bh @32768, Bl @49152; stage stride 65536.
__global__ __launch_bounds__(256)
void gemm_tc_kernel(const uint32_t* __restrict__ aph, const uint32_t* __restrict__ apl,
                    const uint32_t* __restrict__ bph, const uint32_t* __restrict__ bpl,
                    const float* __restrict__ bias, float* __restrict__ C, int KQ) {
    extern __shared__ uint32_t sm[];
    uint32_t sb = smem_u32(sm);
    const int tid = threadIdx.x, lane = tid & 31, wid = tid >> 5;
    const int wm = wid >> 1, wn = wid & 1;
    const int mt = blockIdx.x;
    const int bn8 = blockIdx.y * 16;
    const int nch = KQ >> 2;

    const uint32_t* agh = aph + (size_t)mt * KQ * 1024;
    const uint32_t* agl = apl + (size_t)mt * KQ * 1024;

    float acc[2][8][4];
    #pragma unroll
    for (int mi = 0; mi < 2; mi++)
        #pragma unroll
        for (int ni = 0; ni < 8; ni++)
            #pragma unroll
            for (int r = 0; r < 4; r++) acc[mi][ni][r] = 0.f;

    // chunk loader: 16 cp.async x 16B per thread
    auto load_chunk = [&](int ch, int s) {
        uint32_t base = sb + s * 65536;
        #pragma unroll
        for (int i = 0; i < 4; i++) {
            CP_ASYNC16(base + i * 4096 + tid * 16,          agh + ch * 4096 + i * 1024 + tid * 4);
            CP_ASYNC16(base + 16384 + i * 4096 + tid * 16,  agl + ch * 4096 + i * 1024 + tid * 4);
            CP_ASYNC16(base + 32768 + i * 4096 + tid * 16,  bph + (ch * 4 + i) * 2048 + bn8 * 64 + tid * 4);
            CP_ASYNC16(base + 49152 + i * 4096 + tid * 16,  bpl + (ch * 4 + i) * 2048 + bn8 * 64 + tid * 4);
        }
        CP_COMMIT;
    };

    load_chunk(0, 0);

    for (int ch = 0; ch < nch; ch++) {
        int s = ch & 1;
        if (ch + 1 < nch) {
            load_chunk(ch + 1, s ^ 1);
            CP_WAIT(1);
        } else {
            CP_WAIT(0);
        }
        __syncthreads();

        const uint32_t* st = sm + s * 16384;
        #pragma unroll
        for (int k8 = 0; k8 < 4; k8++) {
            uint32_t ah[2][4], al[2][4];
            #pragma unroll
            for (int mi = 0; mi < 2; mi++) {
                int m16 = wm * 2 + mi;
                uint4 vh = *(const uint4*)(st + (k8 * 8 + m16) * 128 + lane * 4);
                uint4 vl = *(const uint4*)(st + 4096 + (k8 * 8 + m16) * 128 + lane * 4);
                ah[mi][0] = vh.x; ah[mi][1] = vh.y; ah[mi][2] = vh.z; ah[mi][3] = vh.w;
                al[mi][0] = vl.x; al[mi][1] = vl.y; al[mi][2] = vl.z; al[mi][3] = vl.w;
            }
            #pragma unroll
            for (int ni = 0; ni < 8; ni++) {
                int n8l = wn * 8 + ni;
                uint2 bhv = *(const uint2*)(st + 8192 + k8 * 1024 + n8l * 64 + lane * 2);
                uint2 blv = *(const uint2*)(st + 12288 + k8 * 1024 + n8l * 64 + lane * 2);
                uint32_t bh[2] = {bhv.x, bhv.y}, bl[2] = {blv.x, blv.y};
                #pragma unroll
                for (int mi = 0; mi < 2; mi++) {
                    mma_tf32(acc[mi][ni], al[mi], bh);
                    mma_tf32(acc[mi][ni], ah[mi], bl);
                    mma_tf32(acc[mi][ni], ah[mi], bh);
                }
            }
        }
        __syncthreads();
    }

    // epilogue
    const int g = lane >> 2, tig = lane & 3;
    #pragma unroll
    for (int mi = 0; mi < 2; mi++) {
        int row = mt * 128 + wm * 32 + mi * 16 + g;
        #pragma unroll
        for (int ni = 0; ni < 8; ni++) {
            int col = blockIdx.y * 128 + wn * 64 + ni * 8 + tig * 2;
            float b0 = __ldg(bias + col), b1 = __ldg(bias + col + 1);
            if (row < NN)
                *(float2*)(C + (size_t)row * 256 + col) =
                    make_float2(acc[mi][ni][0] + b0, acc[mi][ni][1] + b1);
            if (row + 8 < NN)
                *(float2*)(C + (size_t)(row + 8) * 256 + col) =
                    make_float2(acc[mi][ni][2] + b0, acc[mi][ni][3] + b1);
        }
    }
}

// ---------------- GATv2 aggregation: one warp per dst node ------------------
__global__ __launch_bounds__(256)
void gat_agg_kernel(const float* __restrict__ xl, const float* __restrict__ xr,
                    const float* __restrict__ edge_attr,
                    const int* __restrict__ srcarr,
                    const float* __restrict__ We, const float* __restrict__ att,
                    const float* __restrict__ bias, float* __restrict__ out) {
    int warp = (blockIdx.x * blockDim.x + threadIdx.x) >> 5;
    if (warp >= NN) return;
    int lane  = threadIdx.x & 31;
    int node  = warp;
    int jbase = lane * 8;

    float we0[8], we1[8], we2[8], attv[8], xrv[8];
    #pragma unroll
    for (int i = 0; i < 8; i++) {
        int j = jbase + i;
        we0[i]  = We[j];
        we1[i]  = We[256 + j];
        we2[i]  = We[512 + j];
        attv[i] = att[j];
        xrv[i]  = xr[(size_t)node * HC + j];
    }

    float mx = -1e30f, denom = 0.f;
    float acc[8] = {};
    float sea0 = 0.f, sea1 = 0.f, sea2 = 0.f;
    int e0 = g_off[node], e1 = g_off[node + 1];

    for (int t = e0; t <= e1; t++) {      // last iteration = self loop
        int s; float ea0, ea1, ea2;
        if (t < e1) {
            int e = g_csr[t];
            s = srcarr[e];
            ea0 = edge_attr[e * 3 + 0];
            ea1 = edge_attr[e * 3 + 1];
            ea2 = edge_attr[e * 3 + 2];
            sea0 += ea0; sea1 += ea1; sea2 += ea2;
        } else {
            s = node;
            float inv = 1.f / fmaxf((float)(e1 - e0), 1.f);
            ea0 = sea0 * inv; ea1 = sea1 * inv; ea2 = sea2 * inv;
        }
        float xlv[8];
        const float4* p = (const float4*)(xl + (size_t)s * HC + jbase);
        float4 v0 = p[0], v1 = p[1];
        xlv[0] = v0.x; xlv[1] = v0.y; xlv[2] = v0.z; xlv[3] = v0.w;
        xlv[4] = v1.x; xlv[5] = v1.y; xlv[6] = v1.z; xlv[7] = v1.w;

        float part = 0.f;
        #pragma unroll
        for (int i = 0; i < 8; i++) {
            float m = xlv[i] + xrv[i] + ea0 * we0[i] + ea1 * we1[i] + ea2 * we2[i];
            m = (m > 0.f) ? m : 0.2f * m;
            part += m * attv[i];
        }
        part += __shfl_xor_sync(0xffffffff, part, 1);
        part += __shfl_xor_sync(0xffffffff, part, 2);
        part += __shfl_xor_sync(0xffffffff, part, 4);
        float alpha = part;

        float nm = fmaxf(mx, alpha);
        float sc = __expf(mx - nm);
        float pw = __expf(alpha - nm);
        denom = denom * sc + pw;
        #pragma unroll
        for (int i = 0; i < 8; i++) acc[i] = acc[i] * sc + pw * xlv[i];
        mx = nm;
    }

    float inv = 1.f / denom;
    #pragma unroll
    for (int i = 0; i < 8; i++) {
        float r = acc[i] * inv;
        r += __shfl_xor_sync(0xffffffff, r, 8);
        r += __shfl_xor_sync(0xffffffff, r, 16);
        acc[i] = r * 0.25f;
    }
    if (lane < 8) {
        #pragma unroll
        for (int i = 0; i < 8; i++) {
            int c = jbase + i;
            out[(size_t)node * CC + c] = fmaxf(acc[i] + bias[c], 0.f);
        }
    }
}

// ---------------- final projection ------------------------------------------
__global__ __launch_bounds__(256)
void mu_kernel(const float* __restrict__ h, const float* __restrict__ Wmu,
               const float* __restrict__ bmu, float* __restrict__ out) {
    __shared__ float sW[CC * LAT];
    __shared__ float sb[LAT];
    int tid = threadIdx.x;
    for (int i = tid; i < CC * LAT; i += 256) sW[i] = Wmu[i];
    if (tid < LAT) sb[tid] = bmu[tid];
    __syncthreads();
    int warp = tid >> 5, lane = tid & 31;
    int node = blockIdx.x * 8 + warp;
    if (node >= NN) return;
    const float* hr = h + (size_t)node * CC;
    float sum = sb[lane];
    #pragma unroll
    for (int c = 0; c < CC; c++)
        sum += hr[c] * sW[c * LAT + lane];
    out[(size_t)node * LAT + lane] = sum;
}

// ---------------- host launcher ---------------------------------------------
extern "C" void kernel_launch(void* const* d_in, const int* in_sizes, int n_in,
                              void* d_out, int out_size) {
    const float* x   = (const float*)d_in[0];
    const int*   ei  = (const int*)  d_in[1];
    const float* ea  = (const float*)d_in[2];
    const float* Wl0 = (const float*)d_in[3];
    const float* bl0 = (const float*)d_in[4];
    const float* Wr0 = (const float*)d_in[5];
    const float* br0 = (const float*)d_in[6];
    const float* We0 = (const float*)d_in[7];
    const float* at0 = (const float*)d_in[8];
    const float* bi0 = (const float*)d_in[9];
    const float* Wl1 = (const float*)d_in[10];
    const float* bl1 = (const float*)d_in[11];
    const float* Wr1 = (const float*)d_in[12];
    const float* br1 = (const float*)d_in[13];
    const float* We1 = (const float*)d_in[14];
    const float* at1 = (const float*)d_in[15];
    const float* bi1 = (const float*)d_in[16];
    const float* Wmu = (const float*)d_in[17];
    const float* bmu = (const float*)d_in[18];
    float* out = (float*)d_out;

    const int* src = ei;
    const int* dst = ei + EE;

    float* xl; cudaGetSymbolAddress((void**)&xl, g_xl);
    float* xr; cudaGetSymbolAddress((void**)&xr, g_xr);
    float* h ; cudaGetSymbolAddress((void**)&h , g_h );
    uint32_t* aph; cudaGetSymbolAddress((void**)&aph, g_aph);
    uint32_t* apl; cudaGetSymbolAddress((void**)&apl, g_apl);
    uint32_t* wph; cudaGetSymbolAddress((void**)&wph, g_wph);
    uint32_t* wpl; cudaGetSymbolAddress((void**)&wpl, g_wpl);

    cudaFuncSetAttribute(gemm_tc_kernel, cudaFuncAttributeMaxDynamicSharedMemorySize, 131072);

    const int SCAN_BLOCKS = (NN + 1023) / 1024;
    dim3 gemm_grid(MT, 2);
    dim3 agg_grid((NN + 7) / 8);

    // launch order: #4 = first gemm (ncu capture target)
    init_kernel<<<(NN + 255) / 256, 256>>>();
    convertA_kernel<<<(MT * 32 * 256 + 255) / 256, 256>>>(x, 256, 32);
    convertW_kernel<<<131072 / 256, 256>>>(Wl0, Wr0, Wl1, Wr1);

    gemm_tc_kernel<<<gemm_grid, 256, 131072>>>(aph, apl, wph + 0 * 65536, wpl + 0 * 65536,
                                               bl0, xl, 32);
    gemm_tc_kernel<<<gemm_grid, 256, 131072>>>(aph, apl, wph + 1 * 65536, wpl + 1 * 65536,
                                               br0, xr, 32);

    edge_deg_kernel<<<(EE + 255) / 256, 256>>>(dst);
    deg_blocksum_kernel<<<SCAN_BLOCKS, 1024>>>();
    bsum_scan_kernel<<<1, 1>>>(SCAN_BLOCKS);
    off_write_kernel<<<SCAN_BLOCKS, 1024>>>();
    csr_fill_kernel<<<(EE + 255) / 256, 256>>>(dst);

    gat_agg_kernel<<<agg_grid, 256>>>(xl, xr, ea, src, We0, at0, bi0, h);

    convertA_kernel<<<(MT * 8 * 256 + 255) / 256, 256>>>(h, 64, 8);
    gemm_tc_kernel<<<gemm_grid, 256, 131072>>>(aph, apl, wph + 2 * 65536, wpl + 2 * 65536,
                                               bl1, xl, 8);
    gemm_tc_kernel<<<gemm_grid, 256, 131072>>>(aph, apl, wph + 3 * 65536, wpl + 3 * 65536,
                                               br1, xr, 8);

    gat_agg_kernel<<<agg_grid, 256>>>(xl, xr, ea, src, We1, at1, bi1, h);

    mu_kernel<<<(NN + 7) / 8, 256>>>(h, Wmu, bmu, out);
}